// round 1
// baseline (speedup 1.0000x reference)
#include <cuda_runtime.h>
#include <stdint.h>

#define N     8192
#define DIM   64
#define BIGF  1e30f

// Scratch (allocation-free rule: __device__ globals)
__device__ float g_D[(size_t)N * (size_t)N];   // 256 MB distance matrix
__device__ float g_sq[N];                       // squared norms

// ---------------------------------------------------------------------------
// Kernel 1: squared norms
// ---------------------------------------------------------------------------
__global__ void norms_kernel(const float* __restrict__ x) {
    int i = blockIdx.x * blockDim.x + threadIdx.x;
    if (i < N) {
        const float4* p = (const float4*)(x + (size_t)i * DIM);
        float s = 0.0f;
        #pragma unroll
        for (int k = 0; k < DIM / 4; k++) {
            float4 v = p[k];
            s += v.x * v.x + v.y * v.y + v.z * v.z + v.w * v.w;
        }
        g_sq[i] = s;
    }
}

// ---------------------------------------------------------------------------
// Kernel 2: D[i][j] = sqrt(max(sq_i + sq_j - 2*x_i.x_j, 0))
// 64x64 output tile per block, 16x16 threads, 4x4 per thread, K=64 fully staged.
// ---------------------------------------------------------------------------
__global__ void dist_kernel(const float* __restrict__ x) {
    __shared__ float As[64][65];
    __shared__ float Bs[64][65];

    const int tx = threadIdx.x, ty = threadIdx.y;
    const int tid = ty * 16 + tx;
    const int bi = blockIdx.y, bj = blockIdx.x;

    // Stage both 64x64 tiles (each thread: 4 float4 per tile)
    #pragma unroll
    for (int i = 0; i < 4; i++) {
        int idx = tid + 256 * i;       // 0..1023
        int r   = idx >> 4;            // row within tile
        int c4  = idx & 15;            // float4 column
        float4 a = ((const float4*)(x + (size_t)(bi * 64 + r) * DIM))[c4];
        As[r][c4 * 4 + 0] = a.x; As[r][c4 * 4 + 1] = a.y;
        As[r][c4 * 4 + 2] = a.z; As[r][c4 * 4 + 3] = a.w;
        float4 b = ((const float4*)(x + (size_t)(bj * 64 + r) * DIM))[c4];
        Bs[r][c4 * 4 + 0] = b.x; Bs[r][c4 * 4 + 1] = b.y;
        Bs[r][c4 * 4 + 2] = b.z; Bs[r][c4 * 4 + 3] = b.w;
    }
    __syncthreads();

    float acc[4][4];
    #pragma unroll
    for (int i = 0; i < 4; i++)
        #pragma unroll
        for (int j = 0; j < 4; j++) acc[i][j] = 0.0f;

    #pragma unroll
    for (int k = 0; k < 64; k++) {
        float a[4], b[4];
        #pragma unroll
        for (int i = 0; i < 4; i++) a[i] = As[ty * 4 + i][k];
        #pragma unroll
        for (int j = 0; j < 4; j++) b[j] = Bs[tx * 4 + j][k];
        #pragma unroll
        for (int i = 0; i < 4; i++)
            #pragma unroll
            for (int j = 0; j < 4; j++)
                acc[i][j] = fmaf(a[i], b[j], acc[i][j]);
    }

    const int row0 = bi * 64 + ty * 4;
    const int col0 = bj * 64 + tx * 4;
    float sqc0 = g_sq[col0 + 0], sqc1 = g_sq[col0 + 1];
    float sqc2 = g_sq[col0 + 2], sqc3 = g_sq[col0 + 3];
    #pragma unroll
    for (int i = 0; i < 4; i++) {
        float sqr = g_sq[row0 + i];
        float4 o;
        o.x = sqrtf(fmaxf(sqr + sqc0 - 2.0f * acc[i][0], 0.0f));
        o.y = sqrtf(fmaxf(sqr + sqc1 - 2.0f * acc[i][1], 0.0f));
        o.z = sqrtf(fmaxf(sqr + sqc2 - 2.0f * acc[i][2], 0.0f));
        o.w = sqrtf(fmaxf(sqr + sqc3 - 2.0f * acc[i][3], 0.0f));
        *(float4*)(g_D + (size_t)(row0 + i) * N + col0) = o;
    }
}

// ---------------------------------------------------------------------------
// Kernel 3: Prim's MST (single persistent block, 1024 threads, 8 verts/thread)
// ---------------------------------------------------------------------------
__device__ __forceinline__ unsigned redux_min_u32(unsigned v) {
    unsigned r;
    asm volatile("redux.sync.min.u32 %0, %1, 0xffffffff;" : "=r"(r) : "r"(v));
    return r;
}

__global__ void __launch_bounds__(1024, 1) prim_kernel(float* __restrict__ out) {
    const int t    = threadIdx.x;
    const int lane = t & 31;
    const int warp = t >> 5;

    // mind for vertices v = t + s*1024, s in [0,8)
    float mind[8];
    #pragma unroll
    for (int s = 0; s < 8; s++) mind[s] = BIGF;
    unsigned intree = (t == 0) ? 1u : 0u;   // vertex 0 starts in the tree

    __shared__ unsigned long long parts[2][32];  // double-buffered warp partials

    unsigned j = 0;  // vertex whose row updates mind this step

    for (int step = 0; step < N - 1; ++step) {
        const float* row = g_D + (size_t)j * N;
        float r[8];
        #pragma unroll
        for (int s = 0; s < 8; s++) r[s] = __ldg(row + t + (s << 10));

        // mind update + local packed (value,index) min over non-tree slots.
        // pack = valbits<<13 | vertex  -> u64 min gives min value, tie -> min index
        unsigned long long best = ~0ull;
        #pragma unroll
        for (int s = 0; s < 8; s++) {
            mind[s] = fminf(mind[s], r[s]);
            if (!((intree >> s) & 1u)) {
                unsigned long long p =
                    ((unsigned long long)__float_as_uint(mind[s]) << 13) |
                    (unsigned)(t + (s << 10));
                best = (p < best) ? p : best;
            }
        }

        // Warp-level two-phase redux: min value bits, then min index among minima
        unsigned vb = (unsigned)(best >> 13);
        unsigned vi = (unsigned)best & 0x1FFFu;
        unsigned wv = redux_min_u32(vb);
        unsigned wi = redux_min_u32((vb == wv) ? vi : 0xFFFFFFFFu);
        if (lane == 0)
            parts[step & 1][warp] = ((unsigned long long)wv << 13) | (unsigned long long)wi;
        __syncthreads();

        // Every warp redundantly reduces the 32 partials -> no second barrier,
        // every thread gets j directly (broadcast LDS, conflict-free).
        unsigned long long p = parts[step & 1][lane];
        unsigned v2 = (unsigned)(p >> 13);
        unsigned i2 = (unsigned)p & 0x1FFFu;
        unsigned gv = redux_min_u32(v2);
        unsigned gi = redux_min_u32((v2 == gv) ? i2 : 0xFFFFFFFFu);

        j = gi;
        if (t == 0) {
            out[2 * step]     = 0.0f;                  // birth
            out[2 * step + 1] = __uint_as_float(gv);   // death = MST edge weight
        }
        if ((j & 1023u) == (unsigned)t) intree |= 1u << (j >> 10);
    }
}

// ---------------------------------------------------------------------------
extern "C" void kernel_launch(void* const* d_in, const int* in_sizes, int n_in,
                              void* d_out, int out_size) {
    const float* x = (const float*)d_in[0];
    float* out = (float*)d_out;

    norms_kernel<<<(N + 255) / 256, 256>>>(x);

    dim3 gblk(16, 16);
    dim3 ggrid(N / 64, N / 64);
    dist_kernel<<<ggrid, gblk>>>(x);

    prim_kernel<<<1, 1024>>>(out);
}